// round 2
// baseline (speedup 1.0000x reference)
#include <cuda_runtime.h>

// PGJANET recurrent scan: B=256, T=2048, H=64, O=2.
// 128 persistent blocks x 256 threads; block owns 2 batch elements.
// Thread (j = tid>>2, s = tid&3): unit j, k-slice s. Weights packed as f32x2
// pairs in registers; dot products via fma.rn.f32x2 (sm_103a FFMA2).
// Slice reduction via warp shuffles; 2 __syncthreads per step; ping-pong h.

#define TB  2048
#define HID 64

typedef unsigned long long u64;

__device__ __forceinline__ u64 pk2(float lo, float hi) {
    u64 r; asm("mov.b64 %0, {%1,%2};" : "=l"(r) : "f"(lo), "f"(hi)); return r;
}
__device__ __forceinline__ void upk2(u64 v, float& lo, float& hi) {
    asm("mov.b64 {%0,%1}, %2;" : "=f"(lo), "=f"(hi) : "l"(v));
}
__device__ __forceinline__ u64 ffma2(u64 a, u64 b, u64 c) {
    u64 d; asm("fma.rn.f32x2 %0, %1, %2, %3;" : "=l"(d) : "l"(a), "l"(b), "l"(c)); return d;
}
__device__ __forceinline__ u64 fadd2(u64 a, u64 b) {
    u64 d; asm("add.rn.f32x2 %0, %1, %2;" : "=l"(d) : "l"(a), "l"(b)); return d;
}
__device__ __forceinline__ float sigf(float v) {           // sigmoid
    return __fdividef(1.f, 1.f + __expf(-v));
}
__device__ __forceinline__ float tanhfast(float v) {       // tanh = 2*sig(2x)-1
    return fmaf(2.f, sigf(2.f * v), -1.f);
}

__global__ void __launch_bounds__(256, 1)
pgjanet_kernel(const float* __restrict__ x,
               const float* __restrict__ h0,
               const float* __restrict__ Wa,  const float* __restrict__ ba,
               const float* __restrict__ Wp1, const float* __restrict__ bp1,
               const float* __restrict__ Wp2, const float* __restrict__ bp2,
               const float* __restrict__ Wf,  const float* __restrict__ bf,
               const float* __restrict__ Wg,  const float* __restrict__ bg,
               const float* __restrict__ Wo,  const float* __restrict__ bo,
               float* __restrict__ out)
{
    __shared__ __align__(16) float4 xb4[TB];        // (i0,q0,i1,q1) per t, 32 KB
    __shared__ __align__(16) float hbuf[2][2][64];  // ping-pong h [buf][batch][unit]
    __shared__ __align__(16) float ubuf[2][64];     // u [batch][unit]

    const int tid  = threadIdx.x;
    const int lane = tid & 31;
    const int wid  = tid >> 5;
    const int j    = tid >> 2;      // hidden unit 0..63
    const int s    = tid & 3;       // k-slice 0..3
    const int b0   = blockIdx.x * 2;
    const int base4 = lane & ~3;

    // ---- weights in registers, packed k-pairs ----
    u64 wa[8], wp1[8], wp2[8];      // slice of 16 k
    {
        const float* A = Wa  + j * 65 + s * 16;
        const float* P = Wp1 + j * 65 + s * 16;
        const float* Q = Wp2 + j * 65 + s * 16;
        #pragma unroll
        for (int i = 0; i < 8; i++) {
            wa[i]  = pk2(A[2*i], A[2*i+1]);
            wp1[i] = pk2(P[2*i], P[2*i+1]);
            wp2[i] = pk2(Q[2*i], Q[2*i+1]);
        }
    }
    u64 wf[16], wg[16];             // slice of 32 k
    {
        const float* F = Wf + j * 128 + s * 32;
        const float* G = Wg + j * 128 + s * 32;
        #pragma unroll
        for (int i = 0; i < 16; i++) {
            wf[i] = pk2(F[2*i], F[2*i+1]);
            wg[i] = pk2(G[2*i], G[2*i+1]);
        }
    }

    // per-lane finalize constants: s==0 -> a, s==1 -> p1, s==2 -> p2 (s==3 mirrors a)
    float wlast, pbias;
    {
        const float* Wl = (s == 1) ? Wp1 : (s == 2) ? Wp2 : Wa;
        const float* bl = (s == 1) ? bp1 : (s == 2) ? bp2 : ba;
        wlast = Wl[j * 65 + 64];
        pbias = bl[j];
    }
    const float bf_r = bf[j], bg_r = bg[j];

    // y-warp constants (warps 0,1 -> batch 0,1)
    float wo0a = 0.f, wo0b = 0.f, wo1a = 0.f, wo1b = 0.f, bo0 = 0.f, bo1 = 0.f;
    if (wid < 2) {
        wo0a = Wo[lane];      wo0b = Wo[lane + 32];
        wo1a = Wo[64 + lane]; wo1b = Wo[64 + lane + 32];
        bo0 = bo[0]; bo1 = bo[1];
    }

    // ---- preload x interleaved + h0 ----
    for (int ti = tid; ti < TB; ti += 256) {
        float2 a0 = ((const float2*)x)[(size_t)b0 * TB + ti];
        float2 a1 = ((const float2*)x)[(size_t)(b0 + 1) * TB + ti];
        xb4[ti] = make_float4(a0.x, a0.y, a1.x, a1.y);
    }
    if (tid < 128)
        hbuf[0][tid >> 6][tid & 63] = h0[(size_t)(b0 + (tid >> 6)) * HID + (tid & 63)];
    __syncthreads();

    float h0r = 0.f, h1r = 0.f;     // lane-0 resident h
    if (s == 0) { h0r = hbuf[0][0][j]; h1r = hbuf[0][1][j]; }

    #pragma unroll 1
    for (int t = 0; t < TB; t++) {
        const int cur = t & 1;

        // ---- y for previous step (warps 0,1; pipelined) ----
        if (wid < 2 && t > 0) {
            float ha = hbuf[cur][wid][lane];
            float hb = hbuf[cur][wid][lane + 32];
            float y0 = ha * wo0a + hb * wo0b;
            float y1 = ha * wo1a + hb * wo1b;
            #pragma unroll
            for (int off = 16; off; off >>= 1) {
                y0 += __shfl_xor_sync(~0u, y0, off);
                y1 += __shfl_xor_sync(~0u, y1, off);
            }
            if (lane == 0)
                ((float2*)out)[(size_t)(b0 + wid) * TB + (t - 1)] =
                    make_float2(y0 + bo0, y1 + bo1);
        }

        // ---- phase 1: a/p1/p2 partial dots (slice s of h) ----
        const float4* hA = (const float4*)(&hbuf[cur][0][s * 16]);
        const float4* hB = (const float4*)(&hbuf[cur][1][s * 16]);
        u64 aA0 = 0, aP10 = 0, aP20 = 0, aA1 = 0, aP11 = 0, aP21 = 0;
        #pragma unroll
        for (int r = 0; r < 4; r++) {
            float4 v0 = hA[r], v1 = hB[r];
            u64 p00 = pk2(v0.x, v0.y), p01 = pk2(v0.z, v0.w);
            u64 p10 = pk2(v1.x, v1.y), p11 = pk2(v1.z, v1.w);
            aA0  = ffma2(wa [2*r], p00, aA0);  aA0  = ffma2(wa [2*r+1], p01, aA0);
            aP10 = ffma2(wp1[2*r], p00, aP10); aP10 = ffma2(wp1[2*r+1], p01, aP10);
            aP20 = ffma2(wp2[2*r], p00, aP20); aP20 = ffma2(wp2[2*r+1], p01, aP20);
            aA1  = ffma2(wa [2*r], p10, aA1);  aA1  = ffma2(wa [2*r+1], p11, aA1);
            aP11 = ffma2(wp1[2*r], p10, aP11); aP11 = ffma2(wp1[2*r+1], p11, aP11);
            aP21 = ffma2(wp2[2*r], p10, aP21); aP21 = ffma2(wp2[2*r+1], p11, aP21);
        }
        // fold k-parity, repack (b0,b1), butterfly over 4 slice lanes
        float e, o;
        upk2(aA0,  e, o); float fA0 = e + o;  upk2(aA1,  e, o); float fA1 = e + o;
        upk2(aP10, e, o); float f10 = e + o;  upk2(aP11, e, o); float f11 = e + o;
        upk2(aP20, e, o); float f20 = e + o;  upk2(aP21, e, o); float f21 = e + o;
        u64 rA = pk2(fA0, fA1), rP1 = pk2(f10, f11), rP2 = pk2(f20, f21);
        rA  = fadd2(rA,  __shfl_xor_sync(~0u, rA,  1));
        rP1 = fadd2(rP1, __shfl_xor_sync(~0u, rP1, 1));
        rP2 = fadd2(rP2, __shfl_xor_sync(~0u, rP2, 1));
        rA  = fadd2(rA,  __shfl_xor_sync(~0u, rA,  2));
        rP1 = fadd2(rP1, __shfl_xor_sync(~0u, rP1, 2));
        rP2 = fadd2(rP2, __shfl_xor_sync(~0u, rP2, 2));

        // per-lane scalar input: s==0 amp, s==1 cos, s==2 sin
        float4 xq = xb4[t];
        float s20 = xq.x * xq.x + xq.y * xq.y;
        float s21 = xq.z * xq.z + xq.w * xq.w;
        float r0 = rsqrtf(s20), r1 = rsqrtf(s21);
        float sel0 = (s == 1) ? xq.x : (s == 2) ? xq.y : s20;
        float sel1 = (s == 1) ? xq.z : (s == 2) ? xq.w : s21;
        float dflt = (s == 1) ? 1.f : 0.f;
        float in0 = (s20 > 0.f) ? sel0 * r0 : dflt;
        float in1 = (s21 > 0.f) ? sel1 * r1 : dflt;

        // gate for this lane's role
        u64 rsel = (s == 1) ? rP1 : (s == 2) ? rP2 : rA;
        float z0, z1; upk2(rsel, z0, z1);
        float tg0 = tanhfast(fmaf(in0, wlast, z0) + pbias);
        float tg1 = tanhfast(fmaf(in1, wlast, z1) + pbias);
        float v0 = tg0 - tg0 * tg0;   // t*(1-t)
        float v1 = tg1 - tg1 * tg1;
        float v0_1 = __shfl_sync(~0u, v0, base4 + 1);
        float v0_2 = __shfl_sync(~0u, v0, base4 + 2);
        float v1_1 = __shfl_sync(~0u, v1, base4 + 1);
        float v1_2 = __shfl_sync(~0u, v1, base4 + 2);
        if (s == 0) {
            ubuf[0][j] = v0 * v0_1 * v0_2;
            ubuf[1][j] = v1 * v1_1 * v1_2;
        }
        __syncthreads();

        // ---- phase 2: f/g partial dots over [h, u] (slice s of 128) ----
        const float4* c0 = (s < 2) ? (const float4*)(&hbuf[cur][0][s * 32])
                                   : (const float4*)(&ubuf[0][(s - 2) * 32]);
        const float4* c1 = (s < 2) ? (const float4*)(&hbuf[cur][1][s * 32])
                                   : (const float4*)(&ubuf[1][(s - 2) * 32]);
        u64 aF0 = 0, aG0 = 0, aF1 = 0, aG1 = 0;
        #pragma unroll
        for (int r = 0; r < 8; r++) {
            float4 v0v = c0[r], v1v = c1[r];
            u64 p00 = pk2(v0v.x, v0v.y), p01 = pk2(v0v.z, v0v.w);
            u64 p10 = pk2(v1v.x, v1v.y), p11 = pk2(v1v.z, v1v.w);
            aF0 = ffma2(wf[2*r], p00, aF0); aF0 = ffma2(wf[2*r+1], p01, aF0);
            aG0 = ffma2(wg[2*r], p00, aG0); aG0 = ffma2(wg[2*r+1], p01, aG0);
            aF1 = ffma2(wf[2*r], p10, aF1); aF1 = ffma2(wf[2*r+1], p11, aF1);
            aG1 = ffma2(wg[2*r], p10, aG1); aG1 = ffma2(wg[2*r+1], p11, aG1);
        }
        upk2(aF0, e, o); float fF0 = e + o;  upk2(aF1, e, o); float fF1 = e + o;
        upk2(aG0, e, o); float fG0 = e + o;  upk2(aG1, e, o); float fG1 = e + o;
        u64 rF = pk2(fF0, fF1), rG = pk2(fG0, fG1);
        rF = fadd2(rF, __shfl_xor_sync(~0u, rF, 1));
        rG = fadd2(rG, __shfl_xor_sync(~0u, rG, 1));
        rF = fadd2(rF, __shfl_xor_sync(~0u, rF, 2));
        rG = fadd2(rG, __shfl_xor_sync(~0u, rG, 2));
        float zf0, zf1, zg0, zg1;
        upk2(rF, zf0, zf1); upk2(rG, zg0, zg1);

        // lane s==0 computes f (sigmoid); lane s==1 computes g (tanh), branch-free
        float y0a = (s == 1) ? 2.f * (zg0 + bg_r) : (zf0 + bf_r);
        float y1a = (s == 1) ? 2.f * (zg1 + bg_r) : (zf1 + bf_r);
        float q0 = sigf(y0a), q1 = sigf(y1a);
        if (s == 1) { q0 = fmaf(2.f, q0, -1.f); q1 = fmaf(2.f, q1, -1.f); }
        float gg0 = __shfl_sync(~0u, q0, base4 + 1);
        float gg1 = __shfl_sync(~0u, q1, base4 + 1);
        if (s == 0) {
            h0r = fmaf(q0, h0r - gg0, gg0);   // f*h + (1-f)*g
            h1r = fmaf(q1, h1r - gg1, gg1);
            hbuf[cur ^ 1][0][j] = h0r;
            hbuf[cur ^ 1][1][j] = h1r;
        }
        __syncthreads();
    }

    // ---- epilogue: y for t = TB-1 (written into hbuf[0]) ----
    if (wid < 2) {
        float ha = hbuf[0][wid][lane];
        float hb = hbuf[0][wid][lane + 32];
        float y0 = ha * wo0a + hb * wo0b;
        float y1 = ha * wo1a + hb * wo1b;
        #pragma unroll
        for (int off = 16; off; off >>= 1) {
            y0 += __shfl_xor_sync(~0u, y0, off);
            y1 += __shfl_xor_sync(~0u, y1, off);
        }
        if (lane == 0)
            ((float2*)out)[(size_t)(b0 + wid) * TB + (TB - 1)] =
                make_float2(y0 + bo0, y1 + bo1);
    }
}

extern "C" void kernel_launch(void* const* d_in, const int* in_sizes, int n_in,
                              void* d_out, int out_size)
{
    const float* x   = (const float*)d_in[0];
    const float* h0  = (const float*)d_in[1];
    const float* Wa  = (const float*)d_in[2];
    const float* ba  = (const float*)d_in[3];
    const float* Wp1 = (const float*)d_in[4];
    const float* bp1 = (const float*)d_in[5];
    const float* Wp2 = (const float*)d_in[6];
    const float* bp2 = (const float*)d_in[7];
    const float* Wf  = (const float*)d_in[8];
    const float* bf  = (const float*)d_in[9];
    const float* Wg  = (const float*)d_in[10];
    const float* bg  = (const float*)d_in[11];
    const float* Wo  = (const float*)d_in[12];
    const float* bo  = (const float*)d_in[13];
    float* out = (float*)d_out;

    pgjanet_kernel<<<128, 256>>>(x, h0, Wa, ba, Wp1, bp1, Wp2, bp2,
                                 Wf, bf, Wg, bg, Wo, bo, out);
}

// round 3
// speedup vs baseline: 1.5687x; 1.5687x over previous
#include <cuda_runtime.h>

// PGJANET recurrent scan: B=256, T=2048, H=64, O=2.
// 256 blocks x 256 threads, ONE batch element per block, 2 blocks co-resident
// per SM (launch_bounds forces <=128 regs). Thread (j = tid&63, s = tid>>6):
// hidden unit j, k-slice s. Weights in registers (112 floats/thread),
// partial-dot reduction via shared memory (broadcast-friendly, no shuffles
// in the recurrence path). Finalize on s==0 warps only, fast exp-based
// sigmoid/tanh. y output pipelined one step behind on warp 7.

#define TB 2048

__device__ __forceinline__ float sigf(float v) {
    return __fdividef(1.f, 1.f + __expf(-v));
}
__device__ __forceinline__ float tanhfast(float v) {
    return fmaf(2.f, sigf(2.f * v), -1.f);
}

__global__ void __launch_bounds__(256, 2)
pgjanet_kernel(const float* __restrict__ x,
               const float* __restrict__ h0,
               const float* __restrict__ Wa,  const float* __restrict__ ba,
               const float* __restrict__ Wp1, const float* __restrict__ bp1,
               const float* __restrict__ Wp2, const float* __restrict__ bp2,
               const float* __restrict__ Wf,  const float* __restrict__ bf,
               const float* __restrict__ Wg,  const float* __restrict__ bg,
               const float* __restrict__ Wo,  const float* __restrict__ bo,
               float* __restrict__ out)
{
    __shared__ __align__(16) float2 xb[TB];          // 16 KB input stream
    __shared__ __align__(16) float hbuf[64];         // h state
    __shared__ __align__(16) float ubuf[64];         // u
    __shared__ __align__(16) float part[3][4][64];   // partial dot sums
    __shared__ float cbuf[8][64];   // walast,w1last,w2last,ba,bp1,bp2,bf,bg
    __shared__ float wob[2][64];    // Wo rows
    __shared__ float bob[2];

    const int tid  = threadIdx.x;
    const int lane = tid & 31;
    const int wid  = tid >> 5;
    const int j    = tid & 63;     // hidden unit
    const int s    = tid >> 6;     // k-slice 0..3
    const int b    = blockIdx.x;

    // ---- weights in registers ----
    float wa[16], wp1[16], wp2[16], wf[32], wg[32];
    {
        const float* A = Wa  + j * 65 + s * 16;
        const float* P = Wp1 + j * 65 + s * 16;
        const float* Q = Wp2 + j * 65 + s * 16;
        #pragma unroll
        for (int i = 0; i < 16; i++) { wa[i] = A[i]; wp1[i] = P[i]; wp2[i] = Q[i]; }
        const float* F = Wf + j * 128 + s * 32;
        const float* G = Wg + j * 128 + s * 32;
        #pragma unroll
        for (int i = 0; i < 32; i++) { wf[i] = F[i]; wg[i] = G[i]; }
    }

    // ---- per-unit constants -> smem (keeps regs under the 128 cap) ----
    if (tid < 64) {
        cbuf[0][tid] = Wa [tid * 65 + 64];
        cbuf[1][tid] = Wp1[tid * 65 + 64];
        cbuf[2][tid] = Wp2[tid * 65 + 64];
        cbuf[3][tid] = ba [tid];
        cbuf[4][tid] = bp1[tid];
        cbuf[5][tid] = bp2[tid];
        cbuf[6][tid] = bf [tid];
        cbuf[7][tid] = bg [tid];
        hbuf[tid] = h0[(size_t)b * 64 + tid];
    }
    if (tid >= 64 && tid < 192) wob[(tid - 64) >> 6][tid & 63] = Wo[tid - 64];
    if (tid >= 192 && tid < 194) bob[tid - 192] = bo[tid - 192];

    // ---- preload x ----
    const float2* xg = (const float2*)x + (size_t)b * TB;
    for (int i = tid; i < TB; i += 256) xb[i] = xg[i];

    float h_res = (s == 0) ? h0[(size_t)b * 64 + j] : 0.f;  // s==0 owns h[j]
    __syncthreads();

    float2* outp = (float2*)out + (size_t)b * TB;

    #pragma unroll 1
    for (int t = 0; t < TB; t++) {
        // ---- y for previous step (warp 7, pipelined; reads h_{t-1}) ----
        if (wid == 7 && t > 0) {
            float ha = hbuf[lane], hb = hbuf[lane + 32];
            float y0 = ha * wob[0][lane] + hb * wob[0][lane + 32];
            float y1 = ha * wob[1][lane] + hb * wob[1][lane + 32];
            #pragma unroll
            for (int off = 16; off; off >>= 1) {
                y0 += __shfl_xor_sync(~0u, y0, off);
                y1 += __shfl_xor_sync(~0u, y1, off);
            }
            if (lane == 0) outp[t - 1] = make_float2(y0 + bob[0], y1 + bob[1]);
        }

        // ---- phase 1: a/p1/p2 partial dots over h slice s (broadcast LDS) ----
        {
            const float4* hp = (const float4*)(hbuf + s * 16);
            float aa = 0.f, ap = 0.f, aq = 0.f;
            #pragma unroll
            for (int r = 0; r < 4; r++) {
                float4 v = hp[r];
                aa = fmaf(wa [4*r+0], v.x, aa); ap = fmaf(wp1[4*r+0], v.x, ap); aq = fmaf(wp2[4*r+0], v.x, aq);
                aa = fmaf(wa [4*r+1], v.y, aa); ap = fmaf(wp1[4*r+1], v.y, ap); aq = fmaf(wp2[4*r+1], v.y, aq);
                aa = fmaf(wa [4*r+2], v.z, aa); ap = fmaf(wp1[4*r+2], v.z, ap); aq = fmaf(wp2[4*r+2], v.z, aq);
                aa = fmaf(wa [4*r+3], v.w, aa); ap = fmaf(wp1[4*r+3], v.w, ap); aq = fmaf(wp2[4*r+3], v.w, aq);
            }
            part[0][s][j] = aa;
            part[1][s][j] = ap;
            part[2][s][j] = aq;
        }
        __syncthreads();

        // ---- finalize u (s==0 warps only: 64 threads, one per unit) ----
        if (s == 0) {
            float2 xq = xb[t];
            float s2 = fmaf(xq.x, xq.x, xq.y * xq.y);
            float ri = rsqrtf(s2);
            float amp, ct, st;
            if (s2 > 0.f) { amp = s2 * ri; ct = xq.x * ri; st = xq.y * ri; }
            else          { amp = 0.f;     ct = 1.f;       st = 0.f; }
            float sa = part[0][0][j] + part[0][1][j] + part[0][2][j] + part[0][3][j];
            float sp = part[1][0][j] + part[1][1][j] + part[1][2][j] + part[1][3][j];
            float sq = part[2][0][j] + part[2][1][j] + part[2][2][j] + part[2][3][j];
            float a  = tanhfast(fmaf(amp, cbuf[0][j], sa + cbuf[3][j]));
            float p1 = tanhfast(fmaf(ct,  cbuf[1][j], sp + cbuf[4][j]));
            float p2 = tanhfast(fmaf(st,  cbuf[2][j], sq + cbuf[5][j]));
            ubuf[j] = (a - a * a) * (p1 - p1 * p1) * (p2 - p2 * p2);
        }
        __syncthreads();

        // ---- phase 2: f/g partial dots over [h,u] slice s (broadcast LDS) ----
        {
            const float4* cp = (s < 2) ? (const float4*)(hbuf + s * 32)
                                       : (const float4*)(ubuf + (s - 2) * 32);
            float af = 0.f, ag = 0.f;
            #pragma unroll
            for (int r = 0; r < 8; r++) {
                float4 v = cp[r];
                af = fmaf(wf[4*r+0], v.x, af); ag = fmaf(wg[4*r+0], v.x, ag);
                af = fmaf(wf[4*r+1], v.y, af); ag = fmaf(wg[4*r+1], v.y, ag);
                af = fmaf(wf[4*r+2], v.z, af); ag = fmaf(wg[4*r+2], v.z, ag);
                af = fmaf(wf[4*r+3], v.w, af); ag = fmaf(wg[4*r+3], v.w, ag);
            }
            part[0][s][j] = af;
            part[1][s][j] = ag;
        }
        __syncthreads();

        // ---- finalize h (s==0 warps only) ----
        if (s == 0) {
            float sf = part[0][0][j] + part[0][1][j] + part[0][2][j] + part[0][3][j];
            float sg = part[1][0][j] + part[1][1][j] + part[1][2][j] + part[1][3][j];
            float f = sigf(sf + cbuf[6][j]);
            float g = tanhfast(sg + cbuf[7][j]);
            h_res = fmaf(f, h_res - g, g);     // f*h + (1-f)*g
            hbuf[j] = h_res;
        }
        __syncthreads();
    }

    // ---- epilogue: y for t = TB-1 ----
    if (wid == 7) {
        float ha = hbuf[lane], hb = hbuf[lane + 32];
        float y0 = ha * wob[0][lane] + hb * wob[0][lane + 32];
        float y1 = ha * wob[1][lane] + hb * wob[1][lane + 32];
        #pragma unroll
        for (int off = 16; off; off >>= 1) {
            y0 += __shfl_xor_sync(~0u, y0, off);
            y1 += __shfl_xor_sync(~0u, y1, off);
        }
        if (lane == 0) outp[TB - 1] = make_float2(y0 + bob[0], y1 + bob[1]);
    }
}

extern "C" void kernel_launch(void* const* d_in, const int* in_sizes, int n_in,
                              void* d_out, int out_size)
{
    const float* x   = (const float*)d_in[0];
    const float* h0  = (const float*)d_in[1];
    const float* Wa  = (const float*)d_in[2];
    const float* ba  = (const float*)d_in[3];
    const float* Wp1 = (const float*)d_in[4];
    const float* bp1 = (const float*)d_in[5];
    const float* Wp2 = (const float*)d_in[6];
    const float* bp2 = (const float*)d_in[7];
    const float* Wf  = (const float*)d_in[8];
    const float* bf  = (const float*)d_in[9];
    const float* Wg  = (const float*)d_in[10];
    const float* bg  = (const float*)d_in[11];
    const float* Wo  = (const float*)d_in[12];
    const float* bo  = (const float*)d_in[13];
    float* out = (float*)d_out;

    pgjanet_kernel<<<256, 256>>>(x, h0, Wa, ba, Wp1, bp1, Wp2, bp2,
                                 Wf, bf, Wg, bg, Wo, bo, out);
}

// round 4
// speedup vs baseline: 2.6478x; 1.6878x over previous
#include <cuda_runtime.h>

// PGJANET recurrent scan: B=256, T=2048, H=64, O=2.
// 128 blocks x 256 threads, 2 batch elements per block (round-1 decomposition,
// no register cap). Thread (j = tid&63, s = tid>>6): unit j, k-slice s.
// Weights in registers (112 floats). Phase 1 computes a/p1/p2 dots AND the
// h-half of f/g dots (all depend only on h); phase 2 is the u-half only.
// u-finalize on warps 0-3, y-output on warps 6-7 (concurrent), h-finalize on
// warps 4-7. Fast exp-based sigmoid/tanh. 4 barriers/step.

#define TB 2048

__device__ __forceinline__ float sigf(float v) {
    return __fdividef(1.f, 1.f + __expf(-v));
}
__device__ __forceinline__ float tanhfast(float v) {
    return fmaf(2.f, sigf(2.f * v), -1.f);
}

__global__ void __launch_bounds__(256, 1)
pgjanet_kernel(const float* __restrict__ x,
               const float* __restrict__ h0,
               const float* __restrict__ Wa,  const float* __restrict__ ba,
               const float* __restrict__ Wp1, const float* __restrict__ bp1,
               const float* __restrict__ Wp2, const float* __restrict__ bp2,
               const float* __restrict__ Wf,  const float* __restrict__ bf,
               const float* __restrict__ Wg,  const float* __restrict__ bg,
               const float* __restrict__ Wo,  const float* __restrict__ bo,
               float* __restrict__ out)
{
    __shared__ __align__(16) float2 xb[2][TB];        // 32 KB
    __shared__ __align__(16) float hbuf[2][64];
    __shared__ __align__(16) float ubuf[2][64];
    __shared__ __align__(16) float part[2][5][4][64]; // [elem][gate][slice][unit]

    const int tid  = threadIdx.x;
    const int lane = tid & 31;
    const int wid  = tid >> 5;
    const int j    = tid & 63;      // hidden unit
    const int s    = tid >> 6;      // k-slice 0..3
    const int b0   = blockIdx.x * 2;

    // ---- weights in registers (112 floats) ----
    float wa[16], wp1[16], wp2[16], wfh[16], wgh[16], wfu[16], wgu[16];
    {
        const float* A = Wa  + j * 65 + s * 16;
        const float* P = Wp1 + j * 65 + s * 16;
        const float* Q = Wp2 + j * 65 + s * 16;
        const float* F = Wf  + j * 128 + s * 16;
        const float* G = Wg  + j * 128 + s * 16;
        #pragma unroll
        for (int i = 0; i < 16; i++) {
            wa[i]  = A[i];  wp1[i] = P[i];  wp2[i] = Q[i];
            wfh[i] = F[i];  wgh[i] = G[i];
            wfu[i] = F[64 + i]; wgu[i] = G[64 + i];
        }
    }

    // ---- finalize constants ----
    // u-finalize: warps 0-3 (tid<128), thread -> (e = tid>>6, j)
    float walast = 0.f, w1last = 0.f, w2last = 0.f, ba_r = 0.f, b1_r = 0.f, b2_r = 0.f;
    if (tid < 128) {
        walast = Wa [j * 65 + 64]; ba_r = ba [j];
        w1last = Wp1[j * 65 + 64]; b1_r = bp1[j];
        w2last = Wp2[j * 65 + 64]; b2_r = bp2[j];
    }
    // h-finalize: warps 4-7 (tid>=128), thread -> (e = (tid>>6)&1, j)
    float bf_r = 0.f, bg_r = 0.f;
    if (tid >= 128) { bf_r = bf[j]; bg_r = bg[j]; }
    // y-output: warps 6,7 -> elem 0,1
    float woA0 = 0.f, woB0 = 0.f, woA1 = 0.f, woB1 = 0.f, bo0 = 0.f, bo1 = 0.f;
    if (wid >= 6) {
        woA0 = Wo[lane];      woB0 = Wo[lane + 32];
        woA1 = Wo[64 + lane]; woB1 = Wo[96 + lane];
        bo0 = bo[0]; bo1 = bo[1];
    }

    // ---- preload x + h0 ----
    {
        const float2* xg0 = (const float2*)x + (size_t)b0 * TB;
        const float2* xg1 = (const float2*)x + (size_t)(b0 + 1) * TB;
        for (int i = tid; i < TB; i += 256) { xb[0][i] = xg0[i]; xb[1][i] = xg1[i]; }
    }
    if (tid < 128) hbuf[tid >> 6][j] = h0[(size_t)(b0 + (tid >> 6)) * 64 + j];
    __syncthreads();

    #pragma unroll 1
    for (int t = 0; t < TB; t++) {
        // ==== phase 1: a/p1/p2 + f/g h-half partial dots (both elems) ====
        {
            const float4* h0p = (const float4*)&hbuf[0][s * 16];
            const float4* h1p = (const float4*)&hbuf[1][s * 16];
            float a0 = 0.f, p0 = 0.f, q0 = 0.f, f0 = 0.f, g0 = 0.f;
            float a1 = 0.f, p1 = 0.f, q1 = 0.f, f1 = 0.f, g1 = 0.f;
            #pragma unroll
            for (int r = 0; r < 4; r++) {
                float4 v0 = h0p[r], v1 = h1p[r];
                #pragma unroll
                for (int c = 0; c < 4; c++) {
                    float w_a = wa[4*r+c], w_p = wp1[4*r+c], w_q = wp2[4*r+c];
                    float w_f = wfh[4*r+c], w_g = wgh[4*r+c];
                    float e0 = (c==0)?v0.x:(c==1)?v0.y:(c==2)?v0.z:v0.w;
                    float e1 = (c==0)?v1.x:(c==1)?v1.y:(c==2)?v1.z:v1.w;
                    a0 = fmaf(w_a, e0, a0); a1 = fmaf(w_a, e1, a1);
                    p0 = fmaf(w_p, e0, p0); p1 = fmaf(w_p, e1, p1);
                    q0 = fmaf(w_q, e0, q0); q1 = fmaf(w_q, e1, q1);
                    f0 = fmaf(w_f, e0, f0); f1 = fmaf(w_f, e1, f1);
                    g0 = fmaf(w_g, e0, g0); g1 = fmaf(w_g, e1, g1);
                }
            }
            part[0][0][s][j] = a0;  part[1][0][s][j] = a1;
            part[0][1][s][j] = p0;  part[1][1][s][j] = p1;
            part[0][2][s][j] = q0;  part[1][2][s][j] = q1;
            part[0][3][s][j] = f0;  part[1][3][s][j] = f1;
            part[0][4][s][j] = g0;  part[1][4][s][j] = g1;
        }
        __syncthreads();

        // ==== u-finalize (warps 0-3) || y output (warps 6-7) ====
        if (tid < 128) {
            const int e = tid >> 6;
            float2 xv = xb[e][t];
            float s2 = fmaf(xv.x, xv.x, xv.y * xv.y);
            float ri = rsqrtf(s2);
            float amp, ct, st;
            if (s2 > 0.f) { amp = s2 * ri; ct = xv.x * ri; st = xv.y * ri; }
            else          { amp = 0.f;     ct = 1.f;       st = 0.f; }
            float sa = part[e][0][0][j] + part[e][0][1][j] + part[e][0][2][j] + part[e][0][3][j];
            float sp = part[e][1][0][j] + part[e][1][1][j] + part[e][1][2][j] + part[e][1][3][j];
            float sq = part[e][2][0][j] + part[e][2][1][j] + part[e][2][2][j] + part[e][2][3][j];
            float av  = tanhfast(fmaf(amp, walast, sa + ba_r));
            float p1v = tanhfast(fmaf(ct,  w1last, sp + b1_r));
            float p2v = tanhfast(fmaf(st,  w2last, sq + b2_r));
            ubuf[e][j] = (av - av * av) * (p1v - p1v * p1v) * (p2v - p2v * p2v);
        } else if (wid >= 6 && t > 0) {
            const int e = wid - 6;
            float ha = hbuf[e][lane], hb = hbuf[e][lane + 32];
            float y0 = ha * woA0 + hb * woB0;
            float y1 = ha * woA1 + hb * woB1;
            #pragma unroll
            for (int off = 16; off; off >>= 1) {
                y0 += __shfl_xor_sync(~0u, y0, off);
                y1 += __shfl_xor_sync(~0u, y1, off);
            }
            if (lane == 0)
                ((float2*)out)[(size_t)(b0 + e) * TB + (t - 1)] =
                    make_float2(y0 + bo0, y1 + bo1);
        }
        __syncthreads();

        // ==== phase 2: f/g u-half partial dots (both elems) ====
        {
            const float4* u0p = (const float4*)&ubuf[0][s * 16];
            const float4* u1p = (const float4*)&ubuf[1][s * 16];
            float cf0 = 0.f, cg0 = 0.f, cf1 = 0.f, cg1 = 0.f;
            #pragma unroll
            for (int r = 0; r < 4; r++) {
                float4 v0 = u0p[r], v1 = u1p[r];
                #pragma unroll
                for (int c = 0; c < 4; c++) {
                    float w_f = wfu[4*r+c], w_g = wgu[4*r+c];
                    float e0 = (c==0)?v0.x:(c==1)?v0.y:(c==2)?v0.z:v0.w;
                    float e1 = (c==0)?v1.x:(c==1)?v1.y:(c==2)?v1.z:v1.w;
                    cf0 = fmaf(w_f, e0, cf0); cf1 = fmaf(w_f, e1, cf1);
                    cg0 = fmaf(w_g, e0, cg0); cg1 = fmaf(w_g, e1, cg1);
                }
            }
            part[0][0][s][j] = cf0;  part[1][0][s][j] = cf1;
            part[0][1][s][j] = cg0;  part[1][1][s][j] = cg1;
        }
        __syncthreads();

        // ==== h-finalize (warps 4-7) ====
        if (tid >= 128) {
            const int e = (tid >> 6) & 1;
            float sf = part[e][0][0][j] + part[e][0][1][j] + part[e][0][2][j] + part[e][0][3][j]
                     + part[e][3][0][j] + part[e][3][1][j] + part[e][3][2][j] + part[e][3][3][j];
            float sg = part[e][1][0][j] + part[e][1][1][j] + part[e][1][2][j] + part[e][1][3][j]
                     + part[e][4][0][j] + part[e][4][1][j] + part[e][4][2][j] + part[e][4][3][j];
            float f = sigf(sf + bf_r);
            float g = tanhfast(sg + bg_r);
            float hold = hbuf[e][j];
            hbuf[e][j] = fmaf(f, hold - g, g);   // f*h + (1-f)*g
        }
        __syncthreads();
    }

    // ---- epilogue: y for t = TB-1 ----
    if (wid >= 6) {
        const int e = wid - 6;
        float ha = hbuf[e][lane], hb = hbuf[e][lane + 32];
        float y0 = ha * woA0 + hb * woB0;
        float y1 = ha * woA1 + hb * woB1;
        #pragma unroll
        for (int off = 16; off; off >>= 1) {
            y0 += __shfl_xor_sync(~0u, y0, off);
            y1 += __shfl_xor_sync(~0u, y1, off);
        }
        if (lane == 0)
            ((float2*)out)[(size_t)(b0 + e) * TB + (TB - 1)] =
                make_float2(y0 + bo0, y1 + bo1);
    }
}

extern "C" void kernel_launch(void* const* d_in, const int* in_sizes, int n_in,
                              void* d_out, int out_size)
{
    const float* x   = (const float*)d_in[0];
    const float* h0  = (const float*)d_in[1];
    const float* Wa  = (const float*)d_in[2];
    const float* ba  = (const float*)d_in[3];
    const float* Wp1 = (const float*)d_in[4];
    const float* bp1 = (const float*)d_in[5];
    const float* Wp2 = (const float*)d_in[6];
    const float* bp2 = (const float*)d_in[7];
    const float* Wf  = (const float*)d_in[8];
    const float* bf  = (const float*)d_in[9];
    const float* Wg  = (const float*)d_in[10];
    const float* bg  = (const float*)d_in[11];
    const float* Wo  = (const float*)d_in[12];
    const float* bo  = (const float*)d_in[13];
    float* out = (float*)d_out;

    pgjanet_kernel<<<128, 256>>>(x, h0, Wa, ba, Wp1, bp1, Wp2, bp2,
                                 Wf, bf, Wg, bg, Wo, bo, out);
}